// round 17
// baseline (speedup 1.0000x reference)
#include <cuda_runtime.h>
#include <cuda_fp16.h>
#include <cstdint>

// ComplexBlockLinear, mma.sync fp16 m16n8k16. Round 17 = Round 14 compute
// path (140.0us) restructured as a grid-stride persistent kernel:
// 304 CTAs (2/SM x 152 SMs), each loops over ~13-14 row-tiles with the
// cp.async chunk pipeline running CONTINUOUSLY across tile boundaries
// (chunk 0 of tile t+304 prefetched under chunk 3 of tile t; epilogue
// overlaps the in-flight loads). Compute/staging/epilogue byte-identical.

#define NBLK 8
#define BS 128
#define HD 1024
#define CTA_M 64
#define KC 32
#define NCHUNK (BS / KC)     // 4
#define THREADS 256
#define NTILES 4096          // 512 row-tiles x 8 blocks
#define GRIDX 304            // 2 CTAs/SM x 152 SMs

// per-stage smem:
//   XR/XI: 2 k16-halves x 64 rows x 16 f32, XOR-group swizzle   8192 B each
//   WR/WI: 32 k-rows x 272 B (128 f16 + 8 pad)                  8704 B each
#define XR_OFF 0
#define XI_OFF 8192
#define WR_OFF 16384
#define WI_OFF 25088
#define STAGE_BYTES 33792
#define SMEM_TOTAL (2 * STAGE_BYTES)   // 67584
#define WROWB 272

// pre-converted weight planes, [nblk*128 k][128 n] f16 (512 KB: L2-resident)
__device__ __align__(16) __half g_wre[NBLK * BS * BS];
__device__ __align__(16) __half g_wim[NBLK * BS * BS];

__device__ __forceinline__ uint32_t smem_u32(const void* p) {
    uint32_t a;
    asm("{ .reg .u64 t; cvta.to.shared.u64 t, %1; cvt.u32.u64 %0, t; }"
        : "=r"(a) : "l"(p));
    return a;
}
__device__ __forceinline__ unsigned pack_h2(float lo, float hi) {
    unsigned d;
    asm("cvt.rn.f16x2.f32 %0, %1, %2;" : "=r"(d) : "f"(hi), "f"(lo));
    return d;
}
__device__ __forceinline__ void cp16(uint32_t dst, const void* src) {
    asm volatile("cp.async.ca.shared.global [%0], [%1], 16;"
                 :: "r"(dst), "l"(src) : "memory");
}
__device__ __forceinline__ void cp_commit() {
    asm volatile("cp.async.commit_group;" ::: "memory");
}
template <int N>
__device__ __forceinline__ void cp_wait() {
    asm volatile("cp.async.wait_group %0;" :: "n"(N) : "memory");
}
__device__ __forceinline__ void ldsm_x4t(unsigned& r0, unsigned& r1,
                                         unsigned& r2, unsigned& r3,
                                         uint32_t addr) {
    asm volatile(
        "ldmatrix.sync.aligned.m8n8.x4.trans.shared.b16 {%0,%1,%2,%3},[%4];"
        : "=r"(r0), "=r"(r1), "=r"(r2), "=r"(r3) : "r"(addr));
}
__device__ __forceinline__ void mma_f16(float* d, const unsigned* a,
                                        unsigned b0, unsigned b1) {
    asm volatile(
        "mma.sync.aligned.m16n8k16.row.col.f32.f16.f16.f32 "
        "{%0,%1,%2,%3},{%4,%5,%6,%7},{%8,%9},{%0,%1,%2,%3};\n"
        : "+f"(d[0]), "+f"(d[1]), "+f"(d[2]), "+f"(d[3])
        : "r"(a[0]), "r"(a[1]), "r"(a[2]), "r"(a[3]), "r"(b0), "r"(b1));
}

// ---- weight conversion: [8,128,128,2] f32 -> planar f16 ----
__global__ void wconv_kernel(const float* __restrict__ w) {
    const int idx = blockIdx.x * 256 + threadIdx.x;   // 0..131071
    const float2 v = ((const float2*)w)[idx];
    g_wre[idx] = __float2half_rn(v.x);
    g_wim[idx] = __float2half_rn(v.y);
}

__global__ __launch_bounds__(THREADS, 2)
void cbl_h16g_kernel(const float* __restrict__ xre,
                     const float* __restrict__ xim,
                     float* __restrict__ out) {
    extern __shared__ char smem[];
    const uint32_t sb = smem_u32(smem);

    const int tid  = threadIdx.x;
    const int lane = tid & 31;
    const int warp = tid >> 5;
    const int wm   = warp >> 2;    // 0..1
    const int wn   = warp & 3;     // 0..3

    float accR[2][4][4], accI[2][4][4];
#pragma unroll
    for (int a = 0; a < 2; a++)
#pragma unroll
        for (int b = 0; b < 4; b++)
#pragma unroll
            for (int c = 0; c < 4; c++) { accR[a][b][c] = 0.f; accI[a][b][c] = 0.f; }

    // stage one chunk (tile tt, chunk cc) into buffer bf
    auto issue = [&](int tt, int cc, int bf) {
        const int trow0 = (tt & 511) * CTA_M;
        const int tnb   = tt >> 9;
        const uint32_t base = sb + bf * STAGE_BYTES;
        const int k0 = cc * KC;
        // X: 2 arrays x 2 halves x 64 rows x 4 groups = 1024 chunks, 4/thread
#pragma unroll
        for (int q = 0; q < 4; ++q) {
            const int e   = q * THREADS + tid;     // 0..1023
            const int arr = e >> 9;                // 0: re, 1: im
            const int s   = (e >> 8) & 1;          // k16 half
            const int r   = (e >> 2) & 63;
            const int t   = e & 3;
            const float* src = (arr ? xim : xre) +
                (size_t)(trow0 + r) * HD + tnb * BS + k0 + s * 16 + t * 4;
            const uint32_t doff = ((s * 64 + r) * 16 + ((t ^ (r & 3)) * 4)) * 4;
            cp16(base + (arr ? XI_OFF : XR_OFF) + doff, src);
        }
        // W f16: 2 arrays x 32 k-rows x 16 chunks = 1024, 4/thread (L2-hit)
#pragma unroll
        for (int q = 0; q < 4; ++q) {
            const int e   = q * THREADS + tid;     // 0..1023
            const int arr = e >> 9;
            const int kk  = (e >> 4) & 31;
            const int c16 = e & 15;
            const __half* src = (arr ? g_wim : g_wre) +
                (size_t)(tnb * BS + k0 + kk) * BS + c16 * 8;
            cp16(base + (arr ? WI_OFF : WR_OFF) + kk * WROWB + c16 * 16, src);
        }
        cp_commit();
    };

    const int g = lane >> 2;
    const int t = lane & 3;
    // ldmatrix.x4 lane base: lanes 0-15 -> WR, 16-31 -> WI; k-lo/k-hi by bit3
    const uint32_t ldsm_kr   = (uint32_t)((lane & 7) + ((lane >> 3) & 1) * 8);
    const uint32_t ldsm_base = ((lane & 16) ? WI_OFF : WR_OFF) + ldsm_kr * WROWB;

    int buf = 0;
    issue(blockIdx.x, 0, 0);   // prologue: first chunk of first tile

#pragma unroll 1
    for (int tt = blockIdx.x; tt < NTILES; tt += GRIDX) {
        const int row0 = (tt & 511) * CTA_M;
        const int nb   = tt >> 9;

#pragma unroll 1
        for (int c = 0; c < NCHUNK; ++c) {
            const bool more_c = (c + 1 < NCHUNK);
            const bool more_t = (tt + GRIDX < NTILES);
            if (more_c)       { issue(tt, c + 1, buf ^ 1);        cp_wait<1>(); }
            else if (more_t)  { issue(tt + GRIDX, 0, buf ^ 1);    cp_wait<1>(); }
            else              { cp_wait<0>(); }
            __syncthreads();

            const uint32_t base = sb + buf * STAGE_BYTES;
            const float* sXR = (const float*)(smem + buf * STAGE_BYTES + XR_OFF);
            const float* sXI = (const float*)(smem + buf * STAGE_BYTES + XI_OFF);

#pragma unroll
            for (int s = 0; s < 2; ++s) {     // two k16 steps per chunk
                // ---- A fragments from f32 X smem (R14 path)
                unsigned ar[2][4], ai[2][4];
#pragma unroll
                for (int mt = 0; mt < 2; ++mt) {
                    const int rr = s * 64 + wm * 32 + mt * 16 + g;
                    const int sz = rr & 3;
                    const int c_lo = (((t >> 1) ^ sz) << 2) + (2 * t & 2);
                    const int c_hi = ((((t >> 1) + 2) ^ sz) << 2) + (2 * t & 2);
                    float2 v;
                    v = *(const float2*)&sXR[rr * 16 + c_lo];
                    ar[mt][0] = pack_h2(v.x, v.y);
                    v = *(const float2*)&sXR[(rr + 8) * 16 + c_lo];
                    ar[mt][1] = pack_h2(v.x, v.y);
                    v = *(const float2*)&sXR[rr * 16 + c_hi];
                    ar[mt][2] = pack_h2(v.x, v.y);
                    v = *(const float2*)&sXR[(rr + 8) * 16 + c_hi];
                    ar[mt][3] = pack_h2(v.x, v.y);
                    v = *(const float2*)&sXI[rr * 16 + c_lo];
                    ai[mt][0] = pack_h2(v.x, v.y);
                    v = *(const float2*)&sXI[(rr + 8) * 16 + c_lo];
                    ai[mt][1] = pack_h2(v.x, v.y);
                    v = *(const float2*)&sXI[rr * 16 + c_hi];
                    ai[mt][2] = pack_h2(v.x, v.y);
                    v = *(const float2*)&sXI[(rr + 8) * 16 + c_hi];
                    ai[mt][3] = pack_h2(v.x, v.y);
                }

                // ---- B fragments: one ldmatrix.x4.trans per n-tile (re+im)
                const uint32_t krow = base + ldsm_base +
                                      (uint32_t)(s * 16) * WROWB;
#pragma unroll
                for (int nt = 0; nt < 4; ++nt) {
                    const uint32_t ncol = (uint32_t)(wn * 32 + nt * 8) * 2;
                    unsigned bR0, bR1, bI0, bI1;
                    ldsm_x4t(bR0, bR1, bI0, bI1, krow + ncol);
                    const unsigned nI0 = bI0 ^ 0x80008000u;
                    const unsigned nI1 = bI1 ^ 0x80008000u;
#pragma unroll
                    for (int mt = 0; mt < 2; ++mt) {
                        mma_f16(accR[mt][nt], ar[mt], bR0, bR1);
                        mma_f16(accR[mt][nt], ai[mt], nI0, nI1);
                        mma_f16(accI[mt][nt], ar[mt], bI0, bI1);
                        mma_f16(accI[mt][nt], ai[mt], bR0, bR1);
                    }
                }
            }
            __syncthreads();   // retire this buffer's readers
            buf ^= 1;
        }

        // ---- epilogue (regs->gmem only; overlaps next tile's cp.asyncs)
#pragma unroll
        for (int mt = 0; mt < 2; ++mt) {
            const int r_lo = row0 + wm * 32 + mt * 16 + (lane >> 2);
#pragma unroll
            for (int nt = 0; nt < 4; ++nt) {
                const int col = nb * BS + wn * 32 + nt * 8 + (lane & 3) * 2;
                float4 v0 = make_float4(accR[mt][nt][0], accI[mt][nt][0],
                                        accR[mt][nt][1], accI[mt][nt][1]);
                float4 v1 = make_float4(accR[mt][nt][2], accI[mt][nt][2],
                                        accR[mt][nt][3], accI[mt][nt][3]);
                *(float4*)(out + ((size_t)r_lo * HD + col) * 2)       = v0;
                *(float4*)(out + ((size_t)(r_lo + 8) * HD + col) * 2) = v1;
                accR[mt][nt][0] = 0.f; accR[mt][nt][1] = 0.f;
                accR[mt][nt][2] = 0.f; accR[mt][nt][3] = 0.f;
                accI[mt][nt][0] = 0.f; accI[mt][nt][1] = 0.f;
                accI[mt][nt][2] = 0.f; accI[mt][nt][3] = 0.f;
            }
        }
    }
}

extern "C" void kernel_launch(void* const* d_in, const int* in_sizes, int n_in,
                              void* d_out, int out_size) {
    const float* xre = (const float*)d_in[0];
    const float* xim = (const float*)d_in[1];
    const float* w   = (const float*)d_in[2];
    float* out       = (float*)d_out;

    wconv_kernel<<<NBLK * BS * BS / 256, 256>>>(w);

    cudaFuncSetAttribute(cbl_h16g_kernel,
                         cudaFuncAttributeMaxDynamicSharedMemorySize, SMEM_TOTAL);
    cbl_h16g_kernel<<<GRIDX, THREADS, SMEM_TOTAL>>>(xre, xim, out);
}